// round 5
// baseline (speedup 1.0000x reference)
#include <cuda_runtime.h>
#include <math.h>

#define NUM_F 39
#define EMBED 64
#define NUM_P 741            // F*(F-1)/2
#define TPB   256
#define ROW_IN_V4  (NUM_F * EMBED / 4)     // 624 float4 per input row
#define ROW_OUT_V4 (NUM_P * EMBED / 4)     // 11856 float4 per output row
#define GRID 1184                          // 148 SMs * 8 CTAs (persistent)

__device__ __forceinline__ void cpa16(float4* dst_smem, const float4* src)
{
    unsigned int d = (unsigned int)__cvta_generic_to_shared(dst_smem);
    asm volatile("cp.async.cg.shared.global [%0], [%1], 16;"
                 :: "r"(d), "l"(src));
}

__global__ __launch_bounds__(TPB, 8)       // <=32 regs -> 8 CTAs/SM
void pairwise_kernel(const float* __restrict__ in, float* __restrict__ out,
                     int batch)
{
    __shared__ float4         s[2][ROW_IN_V4];  // double-buffered input row
    __shared__ unsigned short pij[NUM_P];       // packed pair: j | (i<<8)

    const int tid = threadIdx.x;
    const int b0  = blockIdx.x;

    // Build packed pair table ONCE per persistent CTA.
    for (int p = tid; p < NUM_P; p += TPB) {
        int i = (int)(38.5f - sqrtf(1482.25f - 2.0f * (float)p)); // F=39
        if (i < 0) i = 0;
        while (i * NUM_F - i * (i + 1) / 2 > p) --i;
        while ((i + 1) * NUM_F - (i + 1) * (i + 2) / 2 <= p) ++i;
        int j = p - (i * NUM_F - i * (i + 1) / 2) + i + 1;
        pij[p] = (unsigned short)((i << 8) | j);
    }

    // Prefetch first row into buffer 0.
    if (b0 < batch) {
        const float4* in4 = (const float4*)(in + (size_t)b0 * NUM_F * EMBED);
        for (int k = tid; k < ROW_IN_V4; k += TPB)
            cpa16(&s[0][k], &in4[k]);
    }
    asm volatile("cp.async.commit_group;");

    const int q = tid & 15;
    int buf = 0;
    for (int b = b0; b < batch; b += GRID, buf ^= 1) {
        const int bn = b + GRID;
        const bool has_next = (bn < batch);

        // Prefetch NEXT row into the other buffer (overlaps with the store
        // loop below). The other buffer's previous contents were fully
        // consumed before the __syncthreads() that ended the last iteration.
        if (has_next) {
            const float4* in4 = (const float4*)(in + (size_t)bn * NUM_F * EMBED);
            for (int k = tid; k < ROW_IN_V4; k += TPB)
                cpa16(&s[buf ^ 1][k], &in4[k]);
        }
        asm volatile("cp.async.commit_group;");

        // Wait for CURRENT row (allow the newest group to stay in flight).
        asm volatile("cp.async.wait_group 1;");
        __syncthreads();

        // Stream 741*64 outputs as 11856 coalesced float4 stores.
        float4* out4 = (float4*)(out + (size_t)b * NUM_P * EMBED);
        const float4* sb = s[buf];
        int p = tid >> 4;
        #pragma unroll 2
        for (int f = tid; f < ROW_OUT_V4; f += TPB, p += 16) {
            const unsigned int pk = pij[p];
            const float4 a = sb[(int)(pk >> 8)   * 16 + q];
            const float4 c = sb[(int)(pk & 0xff) * 16 + q];
            float4 r;
            r.x = a.x * c.x;
            r.y = a.y * c.y;
            r.z = a.z * c.z;
            r.w = a.w * c.w;
            out4[f] = r;
        }
        __syncthreads();   // all reads of s[buf] done before it is re-filled
    }
}

extern "C" void kernel_launch(void* const* d_in, const int* in_sizes, int n_in,
                              void* d_out, int out_size)
{
    const float* in  = (const float*)d_in[0];
    float*       out = (float*)d_out;
    const int batch  = in_sizes[0] / (NUM_F * EMBED);   // 4096
    pairwise_kernel<<<GRID, TPB>>>(in, out, batch);
}

// round 6
// speedup vs baseline: 1.0934x; 1.0934x over previous
#include <cuda_runtime.h>
#include <math.h>

#define NUM_F 39
#define EMBED 64
#define NUM_P 741            // F*(F-1)/2
#define TPB   256
#define ROW_IN_V4  (NUM_F * EMBED / 4)     // 624 float4 per input row
#define ROW_OUT_V4 (NUM_P * EMBED / 4)     // 11856 float4 per output row
#define ROWS_PER_CTA 2

__device__ __forceinline__ void cpa16(float4* dst_smem, const float4* src)
{
    unsigned int d = (unsigned int)__cvta_generic_to_shared(dst_smem);
    asm volatile("cp.async.cg.shared.global [%0], [%1], 16;"
                 :: "r"(d), "l"(src));
}

__global__ __launch_bounds__(TPB, 8)       // <=32 regs -> 8 CTAs/SM
void pairwise_kernel(const float* __restrict__ in, float* __restrict__ out)
{
    __shared__ float4         s[ROWS_PER_CTA][ROW_IN_V4];  // 2 input rows
    __shared__ unsigned short pij[NUM_P];                  // packed (i<<8|j)

    const int tid = threadIdx.x;
    const int b0  = blockIdx.x * ROWS_PER_CTA;

    // 1) Async-load BOTH rows' input (overlaps with table build below).
    const float4* in4 = (const float4*)(in + (size_t)b0 * NUM_F * EMBED);
    #pragma unroll
    for (int k = tid; k < ROWS_PER_CTA * ROW_IN_V4; k += TPB)
        cpa16(&s[0][k], &in4[k]);
    asm volatile("cp.async.commit_group;");

    // 2) Build packed pair table while the loads fly.
    for (int p = tid; p < NUM_P; p += TPB) {
        int i = (int)(38.5f - sqrtf(1482.25f - 2.0f * (float)p)); // F=39
        if (i < 0) i = 0;
        while (i * NUM_F - i * (i + 1) / 2 > p) --i;
        while ((i + 1) * NUM_F - (i + 1) * (i + 2) / 2 <= p) ++i;
        int j = p - (i * NUM_F - i * (i + 1) / 2) + i + 1;
        pij[p] = (unsigned short)((i << 8) | j);
    }
    asm volatile("cp.async.wait_group 0;");
    __syncthreads();                        // the ONLY barrier in the kernel

    // 3) Stream both rows' outputs: barrier-free coalesced float4 stores.
    const int q = tid & 15;
    #pragma unroll
    for (int r = 0; r < ROWS_PER_CTA; ++r) {
        float4* out4 = (float4*)(out + (size_t)(b0 + r) * NUM_P * EMBED);
        const float4* sb = s[r];
        int p = tid >> 4;
        #pragma unroll 2
        for (int f = tid; f < ROW_OUT_V4; f += TPB, p += 16) {
            const unsigned int pk = pij[p];
            const float4 a = sb[(int)(pk >> 8)   * 16 + q];
            const float4 c = sb[(int)(pk & 0xff) * 16 + q];
            float4 v;
            v.x = a.x * c.x;
            v.y = a.y * c.y;
            v.z = a.z * c.z;
            v.w = a.w * c.w;
            out4[f] = v;
        }
    }
}

extern "C" void kernel_launch(void* const* d_in, const int* in_sizes, int n_in,
                              void* d_out, int out_size)
{
    const float* in  = (const float*)d_in[0];
    float*       out = (float*)d_out;
    const int batch  = in_sizes[0] / (NUM_F * EMBED);   // 4096
    pairwise_kernel<<<batch / ROWS_PER_CTA, TPB>>>(in, out);
}

// round 7
// speedup vs baseline: 1.1122x; 1.0171x over previous
#include <cuda_runtime.h>

#define NUM_F 39
#define EMBED 64
#define NUM_P 741            // F*(F-1)/2
#define TPB   256
#define ROW_IN_V4  (NUM_F * EMBED / 4)     // 624 float4 per input row
#define ROW_OUT_V4 (NUM_P * EMBED / 4)     // 11856 float4 per output row

// Compile-time pair table: p -> (i<<8 | j), strict upper triangle, row-major.
struct PairTable {
    unsigned short v[NUM_P];
};
static constexpr PairTable make_table() {
    PairTable t{};
    int p = 0;
    for (int i = 0; i < NUM_F; ++i)
        for (int j = i + 1; j < NUM_F; ++j)
            t.v[p++] = (unsigned short)((i << 8) | j);
    return t;
}
__constant__ PairTable PIJ = make_table();

__global__ __launch_bounds__(TPB, 8)       // <=32 regs -> 8 CTAs/SM
void pairwise_kernel(const float* __restrict__ in, float* __restrict__ out)
{
    __shared__ float4 s[ROW_IN_V4];        // 9984 B: one batch row

    const int b   = blockIdx.x;
    const int tid = threadIdx.x;

    // 1) Stage this batch row's input into smem (float4, coalesced)
    const float4* in4 = (const float4*)(in + (size_t)b * NUM_F * EMBED);
    #pragma unroll
    for (int k = tid; k < ROW_IN_V4; k += TPB)
        s[k] = in4[k];
    __syncthreads();                       // the only barrier

    // 2) Stream 741*64 outputs as 11856 coalesced float4 stores.
    //    Pair indices come from the constant-memory table (LDC broadcast:
    //    only 2 distinct p per warp per iteration).
    float4* out4 = (float4*)(out + (size_t)b * NUM_P * EMBED);
    const int q = tid & 15;
    int p = tid >> 4;
    #pragma unroll 2
    for (int f = tid; f < ROW_OUT_V4; f += TPB, p += 16) {
        const unsigned int pk = PIJ.v[p];
        const float4 a = s[(int)(pk >> 8)   * 16 + q];
        const float4 c = s[(int)(pk & 0xff) * 16 + q];
        float4 r;
        r.x = a.x * c.x;
        r.y = a.y * c.y;
        r.z = a.z * c.z;
        r.w = a.w * c.w;
        out4[f] = r;
    }
}

extern "C" void kernel_launch(void* const* d_in, const int* in_sizes, int n_in,
                              void* d_out, int out_size)
{
    const float* in  = (const float*)d_in[0];
    float*       out = (float*)d_out;
    const int batch  = in_sizes[0] / (NUM_F * EMBED);   // 4096
    pairwise_kernel<<<batch, TPB>>>(in, out);
}